// round 14
// baseline (speedup 1.0000x reference)
#include <cuda_runtime.h>
#include <cuda_fp16.h>
#include <math.h>
#include <stdint.h>

// Problem dims
#define B_   8
#define S_   2048
#define D_   768
#define H_   3072
#define NT_  (B_ * S_)         // 16384 tokens
#define EPS_ 1e-5f

// ---------------------------------------------------------------------------
// Scratch (device globals) — activations fp16
// ---------------------------------------------------------------------------
__device__ unsigned short g_h  [NT_ * D_];                // LN1 out
__device__ unsigned short g_qk [NT_ * 2 * D_];            // [NT, 1536]: q | k
__device__ unsigned short g_vt [NT_ * D_];                // [D, B*S]
__device__ unsigned short g_sch[(size_t)B_ * S_ * S_];    // fp16 scores -> probs (in-place)
__device__ unsigned short g_y  [NT_ * D_];
__device__ float          g_x1 [NT_ * D_];
__device__ unsigned short g_h2 [NT_ * D_];
__device__ unsigned short g_m  [(size_t)NT_ * H_];
// transposed weights [N,K] fp16
__device__ unsigned short g_wqkt[2 * D_ * D_];            // [1536, 768]
__device__ unsigned short g_wvt [D_ * D_];
__device__ unsigned short g_wot [D_ * D_];
__device__ unsigned short g_wfct[H_ * D_];
__device__ unsigned short g_wprojt[D_ * H_];
__device__ float          g_bqk[2 * D_];

// ---------------------------------------------------------------------------
// PTX helpers
// ---------------------------------------------------------------------------
__device__ __forceinline__ void cp16(uint32_t dst, const void* src) {
    asm volatile("cp.async.cg.shared.global [%0], [%1], 16;" :: "r"(dst), "l"(src));
}
__device__ __forceinline__ void cp_commit() { asm volatile("cp.async.commit_group;" ::: "memory"); }
__device__ __forceinline__ void cp_wait0()  { asm volatile("cp.async.wait_group 0;"  ::: "memory"); }
__device__ __forceinline__ void cp_wait1()  { asm volatile("cp.async.wait_group 1;"  ::: "memory"); }

__device__ __forceinline__ void ldm4(uint32_t (&r)[4], uint32_t addr) {
    asm volatile("ldmatrix.sync.aligned.m8n8.x4.shared.b16 {%0,%1,%2,%3}, [%4];"
                 : "=r"(r[0]), "=r"(r[1]), "=r"(r[2]), "=r"(r[3]) : "r"(addr));
}
__device__ __forceinline__ void mma16816(float (&c)[4], const uint32_t (&a)[4],
                                         const uint32_t (&b)[2]) {
    asm volatile("mma.sync.aligned.m16n8k16.row.col.f32.f16.f16.f32 "
                 "{%0,%1,%2,%3}, {%4,%5,%6,%7}, {%8,%9}, {%0,%1,%2,%3};"
                 : "+f"(c[0]), "+f"(c[1]), "+f"(c[2]), "+f"(c[3])
                 : "r"(a[0]), "r"(a[1]), "r"(a[2]), "r"(a[3]), "r"(b[0]), "r"(b[1]));
}
__device__ __forceinline__ uint32_t pack2h(__half a, __half b) {
    return ((uint32_t)__half_as_ushort(b) << 16) | __half_as_ushort(a);
}

// ---------------------------------------------------------------------------
// Tensor-core GEMM: C[M,N] = alpha * (sum_k A[M,K]*B[N,K]) (+bias)(+gelu)(+res)
// CTA tile 128x256, BK=64, 256 threads (8 warps, 2x4), warp tile 64x64.
// Warp tile 64x64 balances smem crossbar (128 B/cyc) with tensor pipe ->
// crossbar no longer caps tensor utilization (was 67% ceiling at 64x32).
// 1 CTA/SM, ~175 regs/thread (fits 255-reg cap at 256 threads).
// 3-stage cp.async, one __syncthreads per 4 k16-steps.
// PITCH=144 (stride 9 x 16B) -> ldmatrix conflict-free.
// BIASM: 0 none, 1 col, 2 row.  OUTK: 0 fp32, 1 fp16
// ---------------------------------------------------------------------------
#define PITCH   144
#define ATILEB  (128 * PITCH)                 // 18432
#define BTILEB  (256 * PITCH)                 // 36864
#define STAGEB  (ATILEB + BTILEB)             // 55296
#define NSTAGE  3
#define SMEM_GEMM (NSTAGE * STAGEB)           // 165888 (1 CTA/SM)

__device__ __forceinline__ void load_stage(uint32_t so, const __half* gA,
                                           long ldA, const __half* gB,
                                           long ldB, int k0) {
    int tid = threadIdx.x;
#pragma unroll
    for (int i = 0; i < 4; i++) {            // A: 128 rows x 64 cols
        int idx = tid + i * 256;
        int row = idx >> 3, ch = idx & 7;
        cp16(so + row * PITCH + ch * 16, gA + (long)row * ldA + k0 + ch * 8);
    }
#pragma unroll
    for (int i = 0; i < 8; i++) {            // B: 256 rows x 64 cols
        int idx = tid + i * 256;
        int row = idx >> 3, ch = idx & 7;
        cp16(so + ATILEB + row * PITCH + ch * 16, gB + (long)row * ldB + k0 + ch * 8);
    }
}

template <int BIASM, int DOGELU, int DORES, int OUTK>
__global__ void __launch_bounds__(256, 1)
gemm_mma(const __half* __restrict__ A, long ldA, long sA,
         const __half* __restrict__ Bm, long ldB, long sB,
         float* __restrict__ Cf, __half* __restrict__ Ch,
         long ldC, long sC,
         const float* __restrict__ bias, const float* __restrict__ res,
         float alpha, int K)
{
    extern __shared__ char smem[];
    uint32_t sb = (uint32_t)__cvta_generic_to_shared(smem);
    int tid = threadIdx.x, lane = tid & 31, wid = tid >> 5;
    int wm = wid & 1, wn = wid >> 1;                 // 2 x 4 warp grid
    long row0 = (long)blockIdx.y * 128, col0 = (long)blockIdx.x * 256;
    int bz = blockIdx.z;

    const __half* gA = A  + (long)bz * sA + row0 * ldA;
    const __half* gB = Bm + (long)bz * sB + col0 * ldB;

    float acc[4][8][4];
#pragma unroll
    for (int t = 0; t < 4; t++)
#pragma unroll
        for (int j = 0; j < 8; j++)
#pragma unroll
            for (int e = 0; e < 4; e++) acc[t][j][e] = 0.f;

    int a_row  = wm * 64 + (lane & 15);
    int a_ch   = (lane >> 4) * 8;
    int b_row4 = wn * 64 + (lane & 7) + ((lane >> 4) << 3);  // ldm4 covers 2 j's
    int b_ch4  = ((lane >> 3) & 1) * 8;

    int NC = K >> 6;                          // BK = 64
#pragma unroll
    for (int s = 0; s < NSTAGE - 1; s++) {
        if (s < NC) {
            load_stage(sb + s * STAGEB, gA, ldA, gB, ldB, s * 64);
            cp_commit();
        }
    }

    for (int c = 0; c < NC; c++) {
        if (c + 1 < NC) cp_wait1(); else cp_wait0();
        __syncthreads();

        uint32_t s0 = sb + (c % NSTAGE) * STAGEB;

        // ---- k16-step 0 immediately (tensor pipe starts now) ----
        {
            uint32_t br[8][2];
#pragma unroll
            for (int j2 = 0; j2 < 4; j2++) {
                uint32_t r4[4];
                ldm4(r4, sb + (c % NSTAGE) * STAGEB + ATILEB +
                         (b_row4 + j2 * 16) * PITCH + b_ch4 * 2);
                br[j2 * 2 + 0][0] = r4[0]; br[j2 * 2 + 0][1] = r4[1];
                br[j2 * 2 + 1][0] = r4[2]; br[j2 * 2 + 1][1] = r4[3];
            }
            uint32_t ar[4][4];
#pragma unroll
            for (int t = 0; t < 4; t++)
                ldm4(ar[t], s0 + (a_row + t * 16) * PITCH + a_ch * 2);
#pragma unroll
            for (int t = 0; t < 4; t++)
#pragma unroll
                for (int j = 0; j < 8; j++)
                    mma16816(acc[t][j], ar[t], br[j]);
        }

        // ---- prefetch stage c+2 (overlaps with remaining MMAs) ----
        if (c + 2 < NC) {
            load_stage(sb + ((c + 2) % NSTAGE) * STAGEB,
                       gA, ldA, gB, ldB, (c + 2) * 64);
            cp_commit();
        }

        // ---- k16-steps 1..3 ----
#pragma unroll
        for (int kk = 16; kk < 64; kk += 16) {
            uint32_t br[8][2];
#pragma unroll
            for (int j2 = 0; j2 < 4; j2++) {
                uint32_t r4[4];
                ldm4(r4, s0 + ATILEB + (b_row4 + j2 * 16) * PITCH + (b_ch4 + kk) * 2);
                br[j2 * 2 + 0][0] = r4[0]; br[j2 * 2 + 0][1] = r4[1];
                br[j2 * 2 + 1][0] = r4[2]; br[j2 * 2 + 1][1] = r4[3];
            }
            uint32_t ar[4][4];
#pragma unroll
            for (int t = 0; t < 4; t++)
                ldm4(ar[t], s0 + (a_row + t * 16) * PITCH + (a_ch + kk) * 2);
#pragma unroll
            for (int t = 0; t < 4; t++)
#pragma unroll
                for (int j = 0; j < 8; j++)
                    mma16816(acc[t][j], ar[t], br[j]);
        }
    }

    // epilogue from registers, fused ops
#pragma unroll
    for (int t = 0; t < 4; t++)
#pragma unroll
        for (int j = 0; j < 8; j++) {
#pragma unroll
            for (int half = 0; half < 2; half++) {
                long r  = row0 + wm * 64 + t * 16 + (lane >> 2) + half * 8;
                long cc = col0 + wn * 64 + j * 8 + (lane & 3) * 2;
                float v0 = acc[t][j][half * 2 + 0] * alpha;
                float v1 = acc[t][j][half * 2 + 1] * alpha;
                if (BIASM == 1) { v0 += bias[cc]; v1 += bias[cc + 1]; }
                if (BIASM == 2) { float bb = bias[r]; v0 += bb; v1 += bb; }
                if (DOGELU) {
                    v0 = 0.5f * v0 * (1.f + erff(v0 * 0.70710678118654752f));
                    v1 = 0.5f * v1 * (1.f + erff(v1 * 0.70710678118654752f));
                }
                long off = (long)bz * sC + r * ldC + cc;
                if (DORES) {
                    float2 rv = *reinterpret_cast<const float2*>(res + off);
                    v0 += rv.x; v1 += rv.y;
                }
                if (OUTK == 0) {
                    *reinterpret_cast<float2*>(Cf + off) = make_float2(v0, v1);
                } else {
                    *reinterpret_cast<uint32_t*>(Ch + off) =
                        pack2h(__float2half(v0), __float2half(v1));
                }
            }
        }
}

// ---------------------------------------------------------------------------
// Transpose + convert, 4 weights (768x768 each) in one launch via blockIdx.z
// ---------------------------------------------------------------------------
__global__ void __launch_bounds__(256)
tconv4_kernel(const float* __restrict__ s0, const float* __restrict__ s1,
              const float* __restrict__ s2, const float* __restrict__ s3,
              __half* __restrict__ d0, __half* __restrict__ d1,
              __half* __restrict__ d2, __half* __restrict__ d3)
{
    int z = blockIdx.z;
    const float* W = (z == 0) ? s0 : (z == 1) ? s1 : (z == 2) ? s2 : s3;
    __half* o      = (z == 0) ? d0 : (z == 1) ? d1 : (z == 2) ? d2 : d3;
    __shared__ float t[32][33];
    int n0 = blockIdx.x * 32, k0 = blockIdx.y * 32;
    int tx = threadIdx.x & 31, ty = threadIdx.x >> 5;
#pragma unroll
    for (int i = 0; i < 32; i += 8)
        t[ty + i][tx] = W[(long)(k0 + ty + i) * D_ + n0 + tx];
    __syncthreads();
#pragma unroll
    for (int i = 0; i < 32; i += 8)
        o[(long)(n0 + ty + i) * D_ + k0 + tx] = __float2half(t[tx][ty + i]);
}

// Generic single transpose+convert: W[K,N] fp32 -> out[N,K] fp16
__global__ void __launch_bounds__(256)
tconv_kernel(const float* __restrict__ W, __half* __restrict__ o, int K, int N)
{
    __shared__ float t[32][33];
    int n0 = blockIdx.x * 32, k0 = blockIdx.y * 32;
    int tx = threadIdx.x & 31, ty = threadIdx.x >> 5;
#pragma unroll
    for (int i = 0; i < 32; i += 8)
        t[ty + i][tx] = W[(long)(k0 + ty + i) * N + n0 + tx];
    __syncthreads();
#pragma unroll
    for (int i = 0; i < 32; i += 8)
        o[(long)(n0 + ty + i) * K + k0 + tx] = __float2half(t[tx][ty + i]);
}

// concat bq|bk -> bqk[1536]
__global__ void __launch_bounds__(256)
concat2_kernel(const float* __restrict__ a, const float* __restrict__ b,
               float* __restrict__ o)
{
    int i = blockIdx.x * 256 + threadIdx.x;
    if (i < D_) o[i] = a[i];
    else if (i < 2 * D_) o[i] = b[i - D_];
}

// ---------------------------------------------------------------------------
// LayerNorm -> fp16, vectorized: 192 threads/row, float4 loads, uint2 stores
// ---------------------------------------------------------------------------
__global__ void __launch_bounds__(192)
ln_kernel(const float* __restrict__ x, const float* __restrict__ g,
          const float* __restrict__ b, __half* __restrict__ o)
{
    long row = blockIdx.x;
    int t = threadIdx.x;
    float4 v4 = reinterpret_cast<const float4*>(x + row * D_)[t];
    float s  = v4.x + v4.y + v4.z + v4.w;
    float s2 = v4.x * v4.x + v4.y * v4.y + v4.z * v4.z + v4.w * v4.w;
#pragma unroll
    for (int o2 = 16; o2 > 0; o2 >>= 1) {
        s  += __shfl_xor_sync(0xffffffffu, s,  o2);
        s2 += __shfl_xor_sync(0xffffffffu, s2, o2);
    }
    __shared__ float sm[6], sm2[6], stat[2];
    int w = t >> 5, l = t & 31;
    if (l == 0) { sm[w] = s; sm2[w] = s2; }
    __syncthreads();
    if (t == 0) {
        float a = 0.f, c = 0.f;
#pragma unroll
        for (int i = 0; i < 6; i++) { a += sm[i]; c += sm2[i]; }
        float mu = a / (float)D_;
        stat[0] = mu;
        stat[1] = rsqrtf(c / (float)D_ - mu * mu + EPS_);
    }
    __syncthreads();
    float mu = stat[0], rstd = stat[1];
    float4 g4 = reinterpret_cast<const float4*>(g)[t];
    float4 b4 = reinterpret_cast<const float4*>(b)[t];
    uint2 outv;
    outv.x = pack2h(__float2half((v4.x - mu) * rstd * g4.x + b4.x),
                    __float2half((v4.y - mu) * rstd * g4.y + b4.y));
    outv.y = pack2h(__float2half((v4.z - mu) * rstd * g4.z + b4.z),
                    __float2half((v4.w - mu) * rstd * g4.w + b4.w));
    reinterpret_cast<uint2*>(o + row * D_)[t] = outv;
}

// ---------------------------------------------------------------------------
// Softmax over fp16 scores, in place, vectorized: 256 thr x uint4 (8 halves)
// ---------------------------------------------------------------------------
__global__ void __launch_bounds__(256)
softmax_kernel(__half* __restrict__ sc)
{
    long row = blockIdx.x;
    uint4* p4 = reinterpret_cast<uint4*>(sc + row * (long)S_);
    int t = threadIdx.x;
    uint4 pk = p4[t];
    __half2 hh[4];
    hh[0] = *reinterpret_cast<__half2*>(&pk.x);
    hh[1] = *reinterpret_cast<__half2*>(&pk.y);
    hh[2] = *reinterpret_cast<__half2*>(&pk.z);
    hh[3] = *reinterpret_cast<__half2*>(&pk.w);
    float vals[8];
    float mx = -1e30f;
#pragma unroll
    for (int i = 0; i < 4; i++) {
        float2 f2 = __half22float2(hh[i]);
        vals[i * 2 + 0] = f2.x; vals[i * 2 + 1] = f2.y;
        mx = fmaxf(mx, fmaxf(f2.x, f2.y));
    }
#pragma unroll
    for (int o = 16; o > 0; o >>= 1)
        mx = fmaxf(mx, __shfl_xor_sync(0xffffffffu, mx, o));
    __shared__ float sm[8], stat[1];
    int w = t >> 5, l = t & 31;
    if (l == 0) sm[w] = mx;
    __syncthreads();
    if (t == 0) {
        float m2 = sm[0];
#pragma unroll
        for (int i = 1; i < 8; i++) m2 = fmaxf(m2, sm[i]);
        stat[0] = m2;
    }
    __syncthreads();
    float rowmax = stat[0];
    float sum = 0.f;
#pragma unroll
    for (int i = 0; i < 8; i++) {
        float e = __expf(vals[i] - rowmax);
        vals[i] = e; sum += e;
    }
#pragma unroll
    for (int o = 16; o > 0; o >>= 1)
        sum += __shfl_xor_sync(0xffffffffu, sum, o);
    if (l == 0) sm[w] = sum;
    __syncthreads();
    if (t == 0) {
        float a = 0.f;
#pragma unroll
        for (int i = 0; i < 8; i++) a += sm[i];
        stat[0] = 1.f / a;
    }
    __syncthreads();
    float inv = stat[0];
    uint4 outp;
    outp.x = pack2h(__float2half(vals[0] * inv), __float2half(vals[1] * inv));
    outp.y = pack2h(__float2half(vals[2] * inv), __float2half(vals[3] * inv));
    outp.z = pack2h(__float2half(vals[4] * inv), __float2half(vals[5] * inv));
    outp.w = pack2h(__float2half(vals[6] * inv), __float2half(vals[7] * inv));
    p4[t] = outp;
}

// ---------------------------------------------------------------------------
// Launch
// ---------------------------------------------------------------------------
extern "C" void kernel_launch(void* const* d_in, const int* in_sizes, int n_in,
                              void* d_out, int out_size)
{
    const float* x     = (const float*)d_in[0];
    const float* ln1g  = (const float*)d_in[1];
    const float* ln1b  = (const float*)d_in[2];
    const float* ln2g  = (const float*)d_in[3];
    const float* ln2b  = (const float*)d_in[4];
    const float* Wq    = (const float*)d_in[5];
    const float* bq    = (const float*)d_in[6];
    const float* Wk    = (const float*)d_in[7];
    const float* bk    = (const float*)d_in[8];
    const float* Wv    = (const float*)d_in[9];
    const float* bv    = (const float*)d_in[10];
    const float* Wo    = (const float*)d_in[11];
    const float* bo    = (const float*)d_in[12];
    const float* Wfc   = (const float*)d_in[13];
    const float* bfc   = (const float*)d_in[14];
    const float* Wproj = (const float*)d_in[15];
    const float* bproj = (const float*)d_in[16];
    float* out = (float*)d_out;

    auto ga = [](const void* sym) { void* p; cudaGetSymbolAddress(&p, sym); return p; };
    __half *h   = (__half*)ga(g_h);
    __half *qk  = (__half*)ga(g_qk);
    __half *vt  = (__half*)ga(g_vt);
    __half *sch = (__half*)ga(g_sch);
    __half *y   = (__half*)ga(g_y);
    float  *x1  = (float*)ga(g_x1);
    __half *h2  = (__half*)ga(g_h2);
    __half *m   = (__half*)ga(g_m);
    __half *wqkt = (__half*)ga(g_wqkt);
    __half *wvt  = (__half*)ga(g_wvt);
    __half *wot  = (__half*)ga(g_wot);
    __half *wfct = (__half*)ga(g_wfct);
    __half *wpt  = (__half*)ga(g_wprojt);
    float  *bqk  = (float*)ga(g_bqk);

    cudaFuncSetAttribute(gemm_mma<1,0,0,1>, cudaFuncAttributeMaxDynamicSharedMemorySize, SMEM_GEMM);
    cudaFuncSetAttribute(gemm_mma<2,0,0,1>, cudaFuncAttributeMaxDynamicSharedMemorySize, SMEM_GEMM);
    cudaFuncSetAttribute(gemm_mma<0,0,0,1>, cudaFuncAttributeMaxDynamicSharedMemorySize, SMEM_GEMM);
    cudaFuncSetAttribute(gemm_mma<1,0,1,0>, cudaFuncAttributeMaxDynamicSharedMemorySize, SMEM_GEMM);
    cudaFuncSetAttribute(gemm_mma<1,1,0,1>, cudaFuncAttributeMaxDynamicSharedMemorySize, SMEM_GEMM);

    const long sQ  = (long)S_ * D_;
    const long sQK = (long)S_ * 2 * D_;
    const long sS  = (long)S_ * S_;

    // LN1
    ln_kernel<<<NT_, 192>>>(x, ln1g, ln1b, h);

    // transpose+convert Wq,Wk,Wv,Wo (one launch) + concat bias
    tconv4_kernel<<<dim3(24, 24, 4), 256>>>(Wq, Wk, Wv, Wo,
                                            wqkt, wqkt + D_ * D_, wvt, wot);
    concat2_kernel<<<6, 256>>>(bq, bk, bqk);

    // fused qk = h . [Wq|Wk]  -> g_qk [NT, 1536]
    gemm_mma<1,0,0,1><<<dim3(6, 128, 1), 256, SMEM_GEMM>>>(
        h, D_, 0, wqkt, D_, 0, nullptr, qk, 2 * D_, 0, bqk, nullptr, 1.f, D_);

    // v^T = Wv^T . h^T  ([768, 16384], row bias)
    gemm_mma<2,0,0,1><<<dim3(64, 6, 1), 256, SMEM_GEMM>>>(
        wvt, D_, 0, h, D_, 0, nullptr, vt, NT_, 0, bv, nullptr, 1.f, D_);

    // scores = (q . k^T) * 1/sqrt(D)  (batched, fp16 out, scale fused)
    gemm_mma<0,0,0,1><<<dim3(8, 16, B_), 256, SMEM_GEMM>>>(
        qk, 2 * D_, sQK, qk + D_, 2 * D_, sQK,
        nullptr, sch, S_, sS, nullptr, nullptr, 1.0f / sqrtf((float)D_), D_);

    // softmax in-place (fp16, vectorized)
    softmax_kernel<<<B_ * S_, 256>>>(sch);

    // y = probs . v
    gemm_mma<0,0,0,1><<<dim3(3, 16, B_), 256, SMEM_GEMM>>>(
        sch, S_, sS, vt, NT_, S_, nullptr, y, D_, sQ, nullptr, nullptr, 1.f, S_);

    // x1 = x + y . Wo + bo
    gemm_mma<1,0,1,0><<<dim3(3, 128, 1), 256, SMEM_GEMM>>>(
        y, D_, 0, wot, D_, 0, x1, nullptr, D_, 0, bo, x, 1.f, D_);

    // LN2
    ln_kernel<<<NT_, 192>>>(x1, ln2g, ln2b, h2);

    // m = GELU(h2 . Wfc + bfc)
    tconv_kernel<<<dim3(96, 24), 256>>>(Wfc, wfct, D_, H_);
    gemm_mma<1,1,0,1><<<dim3(12, 128, 1), 256, SMEM_GEMM>>>(
        h2, D_, 0, wfct, D_, 0, nullptr, m, H_, 0, bfc, nullptr, 1.f, D_);

    // out = x1 + m . Wproj + bproj
    tconv_kernel<<<dim3(24, 96), 256>>>(Wproj, wpt, H_, D_);
    gemm_mma<1,0,1,0><<<dim3(3, 128, 1), 256, SMEM_GEMM>>>(
        m, H_, 0, wpt, H_, 0, out, nullptr, D_, 0, bproj, x1, 1.f, H_);
}

// round 15
// speedup vs baseline: 1.1098x; 1.1098x over previous
#include <cuda_runtime.h>
#include <cuda_fp16.h>
#include <math.h>
#include <stdint.h>

// Problem dims
#define B_   8
#define S_   2048
#define D_   768
#define H_   3072
#define NT_  (B_ * S_)         // 16384 tokens
#define EPS_ 1e-5f

// ---------------------------------------------------------------------------
// Scratch (device globals) — activations fp16
// ---------------------------------------------------------------------------
__device__ unsigned short g_h  [NT_ * D_];                // LN1 out
__device__ unsigned short g_qk [NT_ * 2 * D_];            // [NT, 1536]: q | k
__device__ unsigned short g_vt [NT_ * D_];                // [D, B*S]
__device__ unsigned short g_sch[(size_t)B_ * S_ * S_];    // fp16 scores -> probs (in-place)
__device__ unsigned short g_y  [NT_ * D_];
__device__ float          g_x1 [NT_ * D_];
__device__ unsigned short g_h2 [NT_ * D_];
__device__ unsigned short g_m  [(size_t)NT_ * H_];
// transposed weights [N,K] fp16
__device__ unsigned short g_wqkt[2 * D_ * D_];            // [1536, 768]
__device__ unsigned short g_wvt [D_ * D_];
__device__ unsigned short g_wot [D_ * D_];
__device__ unsigned short g_wfct[H_ * D_];
__device__ unsigned short g_wprojt[D_ * H_];
__device__ float          g_bqk[2 * D_];

// ---------------------------------------------------------------------------
// PTX helpers
// ---------------------------------------------------------------------------
__device__ __forceinline__ void cp16(uint32_t dst, const void* src) {
    asm volatile("cp.async.cg.shared.global [%0], [%1], 16;" :: "r"(dst), "l"(src));
}
__device__ __forceinline__ void cp_commit() { asm volatile("cp.async.commit_group;" ::: "memory"); }
__device__ __forceinline__ void cp_wait0()  { asm volatile("cp.async.wait_group 0;"  ::: "memory"); }
__device__ __forceinline__ void cp_wait2()  { asm volatile("cp.async.wait_group 2;"  ::: "memory"); }

__device__ __forceinline__ void ldm4(uint32_t (&r)[4], uint32_t addr) {
    asm volatile("ldmatrix.sync.aligned.m8n8.x4.shared.b16 {%0,%1,%2,%3}, [%4];"
                 : "=r"(r[0]), "=r"(r[1]), "=r"(r[2]), "=r"(r[3]) : "r"(addr));
}
__device__ __forceinline__ void mma16816(float (&c)[4], const uint32_t (&a)[4],
                                         const uint32_t (&b)[2]) {
    asm volatile("mma.sync.aligned.m16n8k16.row.col.f32.f16.f16.f32 "
                 "{%0,%1,%2,%3}, {%4,%5,%6,%7}, {%8,%9}, {%0,%1,%2,%3};"
                 : "+f"(c[0]), "+f"(c[1]), "+f"(c[2]), "+f"(c[3])
                 : "r"(a[0]), "r"(a[1]), "r"(a[2]), "r"(a[3]), "r"(b[0]), "r"(b[1]));
}
__device__ __forceinline__ uint32_t pack2h(__half a, __half b) {
    return ((uint32_t)__half_as_ushort(b) << 16) | __half_as_ushort(a);
}

// ---------------------------------------------------------------------------
// Tensor-core GEMM: C[M,N] = alpha * (sum_k A[M,K]*B[N,K]) (+bias)(+gelu)(+res)
// tile 128x128, BK=64, 256 threads (8 warps, 2x4), warp tile 64x32
// 2 CTAs per SM.  3-stage cp.async, one __syncthreads per 4 k16-steps.
// Body interleaves ldm4(A[t]) with its MMAs; B fragments loaded up-front.
// Prefetch split: A-half after step 0, B-half after step 1.
// PITCH=144 (stride 9 x 16B) -> ldmatrix conflict-free.
// BIASM: 0 none, 1 col, 2 row.  OUTK: 0 fp32, 1 fp16
// ---------------------------------------------------------------------------
#define PITCH   144
#define ATILEB  (128 * PITCH)                 // 18432
#define BTILEB  (128 * PITCH)                 // 18432
#define STAGEB  (ATILEB + BTILEB)             // 36864
#define NSTAGE  3
#define SMEM_GEMM (NSTAGE * STAGEB)           // 110592  (x2 CTAs = 221184 <= 228KB)

__device__ __forceinline__ void load_half(uint32_t so, const __half* g,
                                          long ld, int k0) {
    int tid = threadIdx.x;
#pragma unroll
    for (int i = 0; i < 4; i++) {            // 128 rows x 64 cols
        int idx = tid + i * 256;
        int row = idx >> 3, ch = idx & 7;
        cp16(so + row * PITCH + ch * 16, g + (long)row * ld + k0 + ch * 8);
    }
}

template <int BIASM, int DOGELU, int DORES, int OUTK>
__global__ void __launch_bounds__(256, 2)
gemm_mma(const __half* __restrict__ A, long ldA, long sA,
         const __half* __restrict__ Bm, long ldB, long sB,
         float* __restrict__ Cf, __half* __restrict__ Ch,
         long ldC, long sC,
         const float* __restrict__ bias, const float* __restrict__ res,
         float alpha, int K)
{
    extern __shared__ char smem[];
    uint32_t sb = (uint32_t)__cvta_generic_to_shared(smem);
    int tid = threadIdx.x, lane = tid & 31, wid = tid >> 5;
    int wm = wid & 1, wn = wid >> 1;                 // 2 x 4 warp grid
    long row0 = (long)blockIdx.y * 128, col0 = (long)blockIdx.x * 128;
    int bz = blockIdx.z;

    const __half* gA = A  + (long)bz * sA + row0 * ldA;
    const __half* gB = Bm + (long)bz * sB + col0 * ldB;

    float acc[4][4][4];
#pragma unroll
    for (int t = 0; t < 4; t++)
#pragma unroll
        for (int j = 0; j < 4; j++)
#pragma unroll
            for (int e = 0; e < 4; e++) acc[t][j][e] = 0.f;

    int a_row  = wm * 64 + (lane & 15);
    int a_ch   = (lane >> 4) * 8;
    int b_row4 = wn * 32 + (lane & 7) + ((lane >> 4) << 3);  // ldm4 covers 2 j's
    int b_ch4  = ((lane >> 3) & 1) * 8;

    int NC = K >> 6;                          // BK = 64
    // prologue: stages 0,1 (each as two committed halves: A then B)
#pragma unroll
    for (int s = 0; s < NSTAGE - 1; s++) {
        if (s < NC) {
            load_half(sb + s * STAGEB,          gA, ldA, s * 64);
            cp_commit();
            load_half(sb + s * STAGEB + ATILEB, gB, ldB, s * 64);
            cp_commit();
        }
    }

    for (int c = 0; c < NC; c++) {
        // wait so that stage c (both halves) is resident:
        // groups in flight after prologue/steady: up to 4 halves; stage c done
        // when <= 2 newer halves remain.
        if (c + 1 < NC) cp_wait2(); else cp_wait0();
        __syncthreads();

        uint32_t s0 = sb + (c % NSTAGE) * STAGEB;

        // ---- k16-step 0: B frags, then interleaved A/MMA ----
        {
            uint32_t br[4][2];
#pragma unroll
            for (int j2 = 0; j2 < 2; j2++) {
                uint32_t r4[4];
                ldm4(r4, s0 + ATILEB + (b_row4 + j2 * 16) * PITCH + b_ch4 * 2);
                br[j2 * 2 + 0][0] = r4[0]; br[j2 * 2 + 0][1] = r4[1];
                br[j2 * 2 + 1][0] = r4[2]; br[j2 * 2 + 1][1] = r4[3];
            }
#pragma unroll
            for (int t = 0; t < 4; t++) {
                uint32_t ar[4];
                ldm4(ar, s0 + (a_row + t * 16) * PITCH + a_ch * 2);
#pragma unroll
                for (int j = 0; j < 4; j++)
                    mma16816(acc[t][j], ar, br[j]);
            }
        }

        // ---- prefetch A-half of stage c+2 ----
        if (c + 2 < NC) {
            load_half(sb + ((c + 2) % NSTAGE) * STAGEB, gA, ldA, (c + 2) * 64);
            cp_commit();
        }

        // ---- k16-step 1 ----
        {
            uint32_t br[4][2];
#pragma unroll
            for (int j2 = 0; j2 < 2; j2++) {
                uint32_t r4[4];
                ldm4(r4, s0 + ATILEB + (b_row4 + j2 * 16) * PITCH + (b_ch4 + 16) * 2);
                br[j2 * 2 + 0][0] = r4[0]; br[j2 * 2 + 0][1] = r4[1];
                br[j2 * 2 + 1][0] = r4[2]; br[j2 * 2 + 1][1] = r4[3];
            }
#pragma unroll
            for (int t = 0; t < 4; t++) {
                uint32_t ar[4];
                ldm4(ar, s0 + (a_row + t * 16) * PITCH + (a_ch + 16) * 2);
#pragma unroll
                for (int j = 0; j < 4; j++)
                    mma16816(acc[t][j], ar, br[j]);
            }
        }

        // ---- prefetch B-half of stage c+2 ----
        if (c + 2 < NC) {
            load_half(sb + ((c + 2) % NSTAGE) * STAGEB + ATILEB, gB, ldB, (c + 2) * 64);
            cp_commit();
        }

        // ---- k16-steps 2..3 ----
#pragma unroll
        for (int kk = 32; kk < 64; kk += 16) {
            uint32_t br[4][2];
#pragma unroll
            for (int j2 = 0; j2 < 2; j2++) {
                uint32_t r4[4];
                ldm4(r4, s0 + ATILEB + (b_row4 + j2 * 16) * PITCH + (b_ch4 + kk) * 2);
                br[j2 * 2 + 0][0] = r4[0]; br[j2 * 2 + 0][1] = r4[1];
                br[j2 * 2 + 1][0] = r4[2]; br[j2 * 2 + 1][1] = r4[3];
            }
#pragma unroll
            for (int t = 0; t < 4; t++) {
                uint32_t ar[4];
                ldm4(ar, s0 + (a_row + t * 16) * PITCH + (a_ch + kk) * 2);
#pragma unroll
                for (int j = 0; j < 4; j++)
                    mma16816(acc[t][j], ar, br[j]);
            }
        }
    }

    // epilogue from registers, fused ops
#pragma unroll
    for (int t = 0; t < 4; t++)
#pragma unroll
        for (int j = 0; j < 4; j++) {
#pragma unroll
            for (int half = 0; half < 2; half++) {
                long r  = row0 + wm * 64 + t * 16 + (lane >> 2) + half * 8;
                long cc = col0 + wn * 32 + j * 8 + (lane & 3) * 2;
                float v0 = acc[t][j][half * 2 + 0] * alpha;
                float v1 = acc[t][j][half * 2 + 1] * alpha;
                if (BIASM == 1) { v0 += bias[cc]; v1 += bias[cc + 1]; }
                if (BIASM == 2) { float bb = bias[r]; v0 += bb; v1 += bb; }
                if (DOGELU) {
                    v0 = 0.5f * v0 * (1.f + erff(v0 * 0.70710678118654752f));
                    v1 = 0.5f * v1 * (1.f + erff(v1 * 0.70710678118654752f));
                }
                long off = (long)bz * sC + r * ldC + cc;
                if (DORES) {
                    float2 rv = *reinterpret_cast<const float2*>(res + off);
                    v0 += rv.x; v1 += rv.y;
                }
                if (OUTK == 0) {
                    *reinterpret_cast<float2*>(Cf + off) = make_float2(v0, v1);
                } else {
                    *reinterpret_cast<uint32_t*>(Ch + off) =
                        pack2h(__float2half(v0), __float2half(v1));
                }
            }
        }
}

// ---------------------------------------------------------------------------
// Transpose + convert, 4 weights (768x768 each) in one launch via blockIdx.z
// ---------------------------------------------------------------------------
__global__ void __launch_bounds__(256)
tconv4_kernel(const float* __restrict__ s0, const float* __restrict__ s1,
              const float* __restrict__ s2, const float* __restrict__ s3,
              __half* __restrict__ d0, __half* __restrict__ d1,
              __half* __restrict__ d2, __half* __restrict__ d3)
{
    int z = blockIdx.z;
    const float* W = (z == 0) ? s0 : (z == 1) ? s1 : (z == 2) ? s2 : s3;
    __half* o      = (z == 0) ? d0 : (z == 1) ? d1 : (z == 2) ? d2 : d3;
    __shared__ float t[32][33];
    int n0 = blockIdx.x * 32, k0 = blockIdx.y * 32;
    int tx = threadIdx.x & 31, ty = threadIdx.x >> 5;
#pragma unroll
    for (int i = 0; i < 32; i += 8)
        t[ty + i][tx] = W[(long)(k0 + ty + i) * D_ + n0 + tx];
    __syncthreads();
#pragma unroll
    for (int i = 0; i < 32; i += 8)
        o[(long)(n0 + ty + i) * D_ + k0 + tx] = __float2half(t[tx][ty + i]);
}

// Generic single transpose+convert: W[K,N] fp32 -> out[N,K] fp16
__global__ void __launch_bounds__(256)
tconv_kernel(const float* __restrict__ W, __half* __restrict__ o, int K, int N)
{
    __shared__ float t[32][33];
    int n0 = blockIdx.x * 32, k0 = blockIdx.y * 32;
    int tx = threadIdx.x & 31, ty = threadIdx.x >> 5;
#pragma unroll
    for (int i = 0; i < 32; i += 8)
        t[ty + i][tx] = W[(long)(k0 + ty + i) * N + n0 + tx];
    __syncthreads();
#pragma unroll
    for (int i = 0; i < 32; i += 8)
        o[(long)(n0 + ty + i) * K + k0 + tx] = __float2half(t[tx][ty + i]);
}

// concat bq|bk -> bqk[1536]
__global__ void __launch_bounds__(256)
concat2_kernel(const float* __restrict__ a, const float* __restrict__ b,
               float* __restrict__ o)
{
    int i = blockIdx.x * 256 + threadIdx.x;
    if (i < D_) o[i] = a[i];
    else if (i < 2 * D_) o[i] = b[i - D_];
}

// ---------------------------------------------------------------------------
// LayerNorm -> fp16, vectorized: 192 threads/row, float4 loads, uint2 stores
// ---------------------------------------------------------------------------
__global__ void __launch_bounds__(192)
ln_kernel(const float* __restrict__ x, const float* __restrict__ g,
          const float* __restrict__ b, __half* __restrict__ o)
{
    long row = blockIdx.x;
    int t = threadIdx.x;
    float4 v4 = reinterpret_cast<const float4*>(x + row * D_)[t];
    float s  = v4.x + v4.y + v4.z + v4.w;
    float s2 = v4.x * v4.x + v4.y * v4.y + v4.z * v4.z + v4.w * v4.w;
#pragma unroll
    for (int o2 = 16; o2 > 0; o2 >>= 1) {
        s  += __shfl_xor_sync(0xffffffffu, s,  o2);
        s2 += __shfl_xor_sync(0xffffffffu, s2, o2);
    }
    __shared__ float sm[6], sm2[6], stat[2];
    int w = t >> 5, l = t & 31;
    if (l == 0) { sm[w] = s; sm2[w] = s2; }
    __syncthreads();
    if (t == 0) {
        float a = 0.f, c = 0.f;
#pragma unroll
        for (int i = 0; i < 6; i++) { a += sm[i]; c += sm2[i]; }
        float mu = a / (float)D_;
        stat[0] = mu;
        stat[1] = rsqrtf(c / (float)D_ - mu * mu + EPS_);
    }
    __syncthreads();
    float mu = stat[0], rstd = stat[1];
    float4 g4 = reinterpret_cast<const float4*>(g)[t];
    float4 b4 = reinterpret_cast<const float4*>(b)[t];
    uint2 outv;
    outv.x = pack2h(__float2half((v4.x - mu) * rstd * g4.x + b4.x),
                    __float2half((v4.y - mu) * rstd * g4.y + b4.y));
    outv.y = pack2h(__float2half((v4.z - mu) * rstd * g4.z + b4.z),
                    __float2half((v4.w - mu) * rstd * g4.w + b4.w));
    reinterpret_cast<uint2*>(o + row * D_)[t] = outv;
}

// ---------------------------------------------------------------------------
// Softmax over fp16 scores, in place, vectorized: 256 thr x uint4 (8 halves)
// ---------------------------------------------------------------------------
__global__ void __launch_bounds__(256)
softmax_kernel(__half* __restrict__ sc)
{
    long row = blockIdx.x;
    uint4* p4 = reinterpret_cast<uint4*>(sc + row * (long)S_);
    int t = threadIdx.x;
    uint4 pk = p4[t];
    __half2 hh[4];
    hh[0] = *reinterpret_cast<__half2*>(&pk.x);
    hh[1] = *reinterpret_cast<__half2*>(&pk.y);
    hh[2] = *reinterpret_cast<__half2*>(&pk.z);
    hh[3] = *reinterpret_cast<__half2*>(&pk.w);
    float vals[8];
    float mx = -1e30f;
#pragma unroll
    for (int i = 0; i < 4; i++) {
        float2 f2 = __half22float2(hh[i]);
        vals[i * 2 + 0] = f2.x; vals[i * 2 + 1] = f2.y;
        mx = fmaxf(mx, fmaxf(f2.x, f2.y));
    }
#pragma unroll
    for (int o = 16; o > 0; o >>= 1)
        mx = fmaxf(mx, __shfl_xor_sync(0xffffffffu, mx, o));
    __shared__ float sm[8], stat[1];
    int w = t >> 5, l = t & 31;
    if (l == 0) sm[w] = mx;
    __syncthreads();
    if (t == 0) {
        float m2 = sm[0];
#pragma unroll
        for (int i = 1; i < 8; i++) m2 = fmaxf(m2, sm[i]);
        stat[0] = m2;
    }
    __syncthreads();
    float rowmax = stat[0];
    float sum = 0.f;
#pragma unroll
    for (int i = 0; i < 8; i++) {
        float e = __expf(vals[i] - rowmax);
        vals[i] = e; sum += e;
    }
#pragma unroll
    for (int o = 16; o > 0; o >>= 1)
        sum += __shfl_xor_sync(0xffffffffu, sum, o);
    if (l == 0) sm[w] = sum;
    __syncthreads();
    if (t == 0) {
        float a = 0.f;
#pragma unroll
        for (int i = 0; i < 8; i++) a += sm[i];
        stat[0] = 1.f / a;
    }
    __syncthreads();
    float inv = stat[0];
    uint4 outp;
    outp.x = pack2h(__float2half(vals[0] * inv), __float2half(vals[1] * inv));
    outp.y = pack2h(__float2half(vals[2] * inv), __float2half(vals[3] * inv));
    outp.z = pack2h(__float2half(vals[4] * inv), __float2half(vals[5] * inv));
    outp.w = pack2h(__float2half(vals[6] * inv), __float2half(vals[7] * inv));
    p4[t] = outp;
}

// ---------------------------------------------------------------------------
// Launch
// ---------------------------------------------------------------------------
extern "C" void kernel_launch(void* const* d_in, const int* in_sizes, int n_in,
                              void* d_out, int out_size)
{
    const float* x     = (const float*)d_in[0];
    const float* ln1g  = (const float*)d_in[1];
    const float* ln1b  = (const float*)d_in[2];
    const float* ln2g  = (const float*)d_in[3];
    const float* ln2b  = (const float*)d_in[4];
    const float* Wq    = (const float*)d_in[5];
    const float* bq    = (const float*)d_in[6];
    const float* Wk    = (const float*)d_in[7];
    const float* bk    = (const float*)d_in[8];
    const float* Wv    = (const float*)d_in[9];
    const float* bv    = (const float*)d_in[10];
    const float* Wo    = (const float*)d_in[11];
    const float* bo    = (const float*)d_in[12];
    const float* Wfc   = (const float*)d_in[13];
    const float* bfc   = (const float*)d_in[14];
    const float* Wproj = (const float*)d_in[15];
    const float* bproj = (const float*)d_in[16];
    float* out = (float*)d_out;

    auto ga = [](const void* sym) { void* p; cudaGetSymbolAddress(&p, sym); return p; };
    __half *h   = (__half*)ga(g_h);
    __half *qk  = (__half*)ga(g_qk);
    __half *vt  = (__half*)ga(g_vt);
    __half *sch = (__half*)ga(g_sch);
    __half *y   = (__half*)ga(g_y);
    float  *x1  = (float*)ga(g_x1);
    __half *h2  = (__half*)ga(g_h2);
    __half *m   = (__half*)ga(g_m);
    __half *wqkt = (__half*)ga(g_wqkt);
    __half *wvt  = (__half*)ga(g_wvt);
    __half *wot  = (__half*)ga(g_wot);
    __half *wfct = (__half*)ga(g_wfct);
    __half *wpt  = (__half*)ga(g_wprojt);
    float  *bqk  = (float*)ga(g_bqk);

    cudaFuncSetAttribute(gemm_mma<1,0,0,1>, cudaFuncAttributeMaxDynamicSharedMemorySize, SMEM_GEMM);
    cudaFuncSetAttribute(gemm_mma<2,0,0,1>, cudaFuncAttributeMaxDynamicSharedMemorySize, SMEM_GEMM);
    cudaFuncSetAttribute(gemm_mma<0,0,0,1>, cudaFuncAttributeMaxDynamicSharedMemorySize, SMEM_GEMM);
    cudaFuncSetAttribute(gemm_mma<1,0,1,0>, cudaFuncAttributeMaxDynamicSharedMemorySize, SMEM_GEMM);
    cudaFuncSetAttribute(gemm_mma<1,1,0,1>, cudaFuncAttributeMaxDynamicSharedMemorySize, SMEM_GEMM);

    const long sQ  = (long)S_ * D_;
    const long sQK = (long)S_ * 2 * D_;
    const long sS  = (long)S_ * S_;

    // LN1
    ln_kernel<<<NT_, 192>>>(x, ln1g, ln1b, h);

    // transpose+convert Wq,Wk,Wv,Wo (one launch) + concat bias
    tconv4_kernel<<<dim3(24, 24, 4), 256>>>(Wq, Wk, Wv, Wo,
                                            wqkt, wqkt + D_ * D_, wvt, wot);
    concat2_kernel<<<6, 256>>>(bq, bk, bqk);

    // fused qk = h . [Wq|Wk]  -> g_qk [NT, 1536]
    gemm_mma<1,0,0,1><<<dim3(12, 128, 1), 256, SMEM_GEMM>>>(
        h, D_, 0, wqkt, D_, 0, nullptr, qk, 2 * D_, 0, bqk, nullptr, 1.f, D_);

    // v^T = Wv^T . h^T  ([768, 16384], row bias)
    gemm_mma<2,0,0,1><<<dim3(128, 6, 1), 256, SMEM_GEMM>>>(
        wvt, D_, 0, h, D_, 0, nullptr, vt, NT_, 0, bv, nullptr, 1.f, D_);

    // scores = (q . k^T) * 1/sqrt(D)  (batched, fp16 out, scale fused)
    gemm_mma<0,0,0,1><<<dim3(16, 16, B_), 256, SMEM_GEMM>>>(
        qk, 2 * D_, sQK, qk + D_, 2 * D_, sQK,
        nullptr, sch, S_, sS, nullptr, nullptr, 1.0f / sqrtf((float)D_), D_);

    // softmax in-place (fp16, vectorized)
    softmax_kernel<<<B_ * S_, 256>>>(sch);

    // y = probs . v
    gemm_mma<0,0,0,1><<<dim3(6, 16, B_), 256, SMEM_GEMM>>>(
        sch, S_, sS, vt, NT_, S_, nullptr, y, D_, sQ, nullptr, nullptr, 1.f, S_);

    // x1 = x + y . Wo + bo
    gemm_mma<1,0,1,0><<<dim3(6, 128, 1), 256, SMEM_GEMM>>>(
        y, D_, 0, wot, D_, 0, x1, nullptr, D_, 0, bo, x, 1.f, D_);

    // LN2
    ln_kernel<<<NT_, 192>>>(x1, ln2g, ln2b, h2);

    // m = GELU(h2 . Wfc + bfc)
    tconv_kernel<<<dim3(96, 24), 256>>>(Wfc, wfct, D_, H_);
    gemm_mma<1,1,0,1><<<dim3(24, 128, 1), 256, SMEM_GEMM>>>(
        h2, D_, 0, wfct, D_, 0, nullptr, m, H_, 0, bfc, nullptr, 1.f, D_);

    // out = x1 + m . Wproj + bproj
    tconv_kernel<<<dim3(24, 96), 256>>>(Wproj, wpt, H_, D_);
    gemm_mma<1,0,1,0><<<dim3(6, 128, 1), 256, SMEM_GEMM>>>(
        m, H_, 0, wpt, H_, 0, out, nullptr, D_, 0, bproj, x1, 1.f, H_);
}